// round 15
// baseline (speedup 1.0000x reference)
#include <cuda_runtime.h>
#include <cuda_fp16.h>

// WindowAttention: fully tensor-core (fp16 m16n8k16), ldmatrix-native SMEM.
// 50176 windows of [16 tok, 96 ch], H=8, D=12. 8 warps/CTA, 2 CTAs/SM, tile=4 windows.
// QKV B-pack lives in SMEM (LDS.128 @29cyc, was L2 LDG @~250cyc). Proj pack global.
// QF per window: 8 heads x 384 u32 { Q[16 rows] | K | V }.
//   XOR swizzle: row r, slot s -> u32 offset 8r + (s ^ (r & 4)).
//   pad slots 6,7 zero, except V slot6 = (1.0h,0) -> ones col d=12
//   (PV mma emits the softmax row-sum at col 12).
// AF (attn-out, proj-A frags): ks 0-2 alias head-0 block, ks 3-5 alias head-4
//   block, so each head-quad warp overwrites only blocks it alone reads.

#define NWIN   50176
#define NTILES (NWIN / 4)      // 12544
#define L_DIM  3136
#define SCALE  0.28867513459481287f

#define QF_U32   12288                 // 4 windows * 3072
#define OFF_PQ   (QF_U32 * 4)          // 49152: QKV B-pack 13824 u32 = 55296 B
#define OFF_BQ   (OFF_PQ + 55296)      // 104448: qkv_bias 288 f32
#define OFF_BP   (OFF_BQ + 1152)       // proj_bias 96 f32
#define SMEM_BYTES (OFF_BP + 384)      // 105984

typedef unsigned int u32;

__device__ u32 PRJG[12 * 6 * 64];      // proj B-pack (global; small, L1/L2)
__device__ u32 RBH[8 * 128];           // rel-bias half2 [h][i][j2]

__device__ __forceinline__ u32 p16(float a, float b) {
    __half2 h = __floats2half2_rn(a, b);
    return *(u32*)&h;
}
__device__ __forceinline__ u32 smem_u32(const void* p) {
    u32 a;
    asm("{ .reg .u64 t; cvta.to.shared.u64 t, %1; cvt.u32.u64 %0, t; }" : "=r"(a) : "l"(p));
    return a;
}
__device__ __forceinline__ void mma16(float& c0, float& c1, float& c2, float& c3,
                                      u32 a0, u32 a1, u32 a2, u32 a3,
                                      u32 b0, u32 b1) {
    asm volatile(
        "mma.sync.aligned.m16n8k16.row.col.f32.f16.f16.f32 "
        "{%0,%1,%2,%3}, {%4,%5,%6,%7}, {%8,%9}, {%0,%1,%2,%3};"
        : "+f"(c0), "+f"(c1), "+f"(c2), "+f"(c3)
        : "r"(a0), "r"(a1), "r"(a2), "r"(a3), "r"(b0), "r"(b1));
}
__device__ __forceinline__ void ldsm4(u32& r0, u32& r1, u32& r2, u32& r3, u32 a) {
    asm volatile("ldmatrix.sync.aligned.m8n8.x4.shared.b16 {%0,%1,%2,%3}, [%4];"
        : "=r"(r0), "=r"(r1), "=r"(r2), "=r"(r3) : "r"(a));
}
__device__ __forceinline__ void ldsm4t(u32& r0, u32& r1, u32& r2, u32& r3, u32 a) {
    asm volatile("ldmatrix.sync.aligned.m8n8.x4.trans.shared.b16 {%0,%1,%2,%3}, [%4];"
        : "=r"(r0), "=r"(r1), "=r"(r2), "=r"(r3) : "r"(a));
}
// AF block base for a given proj k-step (u32 units within a window block)
__device__ __forceinline__ int afoff(int ks) {
    return (ks < 3) ? ks * 128 : 1536 + (ks - 3) * 128;
}

__global__ __launch_bounds__(256, 2)
void win_attn_kernel(const float* __restrict__ x,
                     const float* __restrict__ mask,
                     const float* __restrict__ qkv_w,
                     const float* __restrict__ qkv_b,
                     const float* __restrict__ proj_w,
                     const float* __restrict__ proj_b,
                     const float* __restrict__ bias_table,
                     float* __restrict__ out)
{
    extern __shared__ char smb[];
    u32*   QF  = (u32*)smb;
    u32*   PQs = (u32*)(smb + OFF_PQ);
    float* BQs = (float*)(smb + OFF_BQ);
    float* BPs = (float*)(smb + OFF_BP);
    const u32 sb = smem_u32(smb);

    const int t = threadIdx.x;

    // ---- One-time staging ----
    for (int i = t; i < QF_U32; i += 256) QF[i] = 0;
    __syncthreads();
    for (int i = t; i < 512; i += 256) {            // V ones col (d=12, slot 6)
        int win = i >> 7, h = (i >> 4) & 7, row = i & 15;
        QF[win * 3072 + h * 384 + 256 + row * 8 + (6 ^ (row & 4))] = 0x00003C00u;
    }
    for (int i = t; i < 36 * 6 * 32; i += 256) {    // QKV B-pack -> SMEM
        int cq = i / 192, r = i % 192, ks = r / 32, lnn = r % 32;
        int gg = lnn >> 2, tt = lnn & 3;
        int k0 = ks * 16 + 2 * tt, n = cq * 8 + gg;
        int dst = cq * 384 + (ks >> 1) * 128 + lnn * 4 + (ks & 1) * 2;
        PQs[dst + 0] = p16(qkv_w[k0 * 288 + n],       qkv_w[(k0 + 1) * 288 + n]);
        PQs[dst + 1] = p16(qkv_w[(k0 + 8) * 288 + n], qkv_w[(k0 + 9) * 288 + n]);
    }
    for (int i = t; i < 12 * 6 * 32; i += 256) {    // proj B-pack -> global
        int cq = i / 192, r = i % 192, ks = r / 32, lnn = r % 32;
        int gg = lnn >> 2, tt = lnn & 3;
        int k0 = ks * 16 + 2 * tt, n = cq * 8 + gg;
        int dst = cq * 384 + (ks >> 1) * 128 + lnn * 4 + (ks & 1) * 2;
        PRJG[dst + 0] = p16(proj_w[k0 * 96 + n],       proj_w[(k0 + 1) * 96 + n]);
        PRJG[dst + 1] = p16(proj_w[(k0 + 8) * 96 + n], proj_w[(k0 + 9) * 96 + n]);
    }
    for (int i = t; i < 1024; i += 256) {
        int h = i >> 7, ii = (i >> 3) & 15, j2 = i & 7;
        int j0 = 2 * j2, j1 = 2 * j2 + 1;
        int d00 = (ii & 3) - (j0 & 3) + 3, d10 = (ii >> 2) - (j0 >> 2) + 3;
        int d01 = (ii & 3) - (j1 & 3) + 3, d11 = (ii >> 2) - (j1 >> 2) + 3;
        RBH[i] = p16(bias_table[(d00 * 7 + d10) * 8 + h],
                     bias_table[(d01 * 7 + d11) * 8 + h]);
    }
    for (int i = t; i < 288; i += 256) BQs[i] = qkv_b[i];
    if (t < 96) BPs[t] = proj_b[t];
    __syncthreads();

    const int wid = t >> 5;
    const int ln  = t & 31;
    const int gi  = ln >> 2;
    const int tg  = ln & 3;
    const int wp  = wid >> 2;       // window pair 0,1 (GEMM phases)
    const int cs  = wid & 3;        // chunk quarter (9 QKV chunks, 3 proj chunks)
    const int aw  = wid >> 1;       // attention: window 0..3
    const int hg  = (wid & 1) * 4;  // attention: head group 0 or 4
    const int xgi = gi & 4;         // epilogue slot-XOR bit

    // ldmatrix lane byte-offsets (within a head block), XOR-swizzled halves
    const int rQ = ln & 15;
    const u32 offQ = (u32)(rQ * 32 + ((((ln >> 4) & 1) << 4) ^ ((rQ & 4) << 2)));
    const int rK = (ln & 7) | (((ln >> 4) & 1) << 3);
    const u32 offK = (u32)(rK * 32 + ((((ln >> 3) & 1) << 4) ^ ((rK & 4) << 2)) + 512);
    const u32 offV = offQ + 1024;
    const int srcln = (ln & ~3) | 2;      // shuffle source: lane holding col 12

    for (int g = blockIdx.x; g < NTILES; g += gridDim.x) {
        // ================= QKV GEMM -> swizzled row-major head blocks ==========
        {
            u32 af[2][6][4];
            #pragma unroll
            for (int wd = 0; wd < 2; wd++) {
                const float* xr = x + ((size_t)g * 64 + (wp * 2 + wd) * 16 + gi) * 96;
                #pragma unroll
                for (int ks = 0; ks < 6; ks++) {
                    float2 v0 = *(const float2*)(xr + ks * 16 + 2 * tg);
                    float2 v1 = *(const float2*)(xr + 768 + ks * 16 + 2 * tg);
                    float2 v2 = *(const float2*)(xr + ks * 16 + 2 * tg + 8);
                    float2 v3 = *(const float2*)(xr + 768 + ks * 16 + 2 * tg + 8);
                    af[wd][ks][0] = p16(v0.x, v0.y);
                    af[wd][ks][1] = p16(v1.x, v1.y);
                    af[wd][ks][2] = p16(v2.x, v2.y);
                    af[wd][ks][3] = p16(v3.x, v3.y);
                }
            }
            // refresh pad slots of heads 0 and 4 (trampled by last tile's AF)
            for (int i = t; i < 768; i += 256) {
                int win = i / 192, r = i % 192;
                int hq = r / 96, r2 = r % 96, sec = r2 >> 5, r3 = r2 & 31;
                int row = r3 >> 1, slot = 6 + (r3 & 1);
                QF[win * 3072 + hq * 4 * 384 + sec * 128 + row * 8 + (slot ^ (row & 4))] =
                    (sec == 2 && slot == 6) ? 0x00003C00u : 0u;
            }
            #pragma unroll 3
            for (int j = 0; j < 9; j++) {
                const int cq = cs * 9 + j;
                float2 bb = *(const float2*)&BQs[cq * 8 + 2 * tg];
                float c[2][4];
                c[0][0] = bb.x; c[0][1] = bb.y; c[0][2] = bb.x; c[0][3] = bb.y;
                c[1][0] = bb.x; c[1][1] = bb.y; c[1][2] = bb.x; c[1][3] = bb.y;
                const u32* bp = PQs + cq * 384 + ln * 4;
                #pragma unroll
                for (int ks2 = 0; ks2 < 3; ks2++) {
                    uint4 bv = *(const uint4*)(bp + ks2 * 128);   // LDS.128
                    mma16(c[0][0], c[0][1], c[0][2], c[0][3],
                          af[0][2*ks2][0], af[0][2*ks2][1], af[0][2*ks2][2], af[0][2*ks2][3],
                          bv.x, bv.y);
                    mma16(c[1][0], c[1][1], c[1][2], c[1][3],
                          af[1][2*ks2][0], af[1][2*ks2][1], af[1][2*ks2][2], af[1][2*ks2][3],
                          bv.x, bv.y);
                    mma16(c[0][0], c[0][1], c[0][2], c[0][3],
                          af[0][2*ks2+1][0], af[0][2*ks2+1][1], af[0][2*ks2+1][2], af[0][2*ks2+1][3],
                          bv.z, bv.w);
                    mma16(c[1][0], c[1][1], c[1][2], c[1][3],
                          af[1][2*ks2+1][0], af[1][2*ks2+1][1], af[1][2*ks2+1][2], af[1][2*ks2+1][3],
                          bv.z, bv.w);
                }
                int col = cq * 8 + 2 * tg;
                int sec = (col >= 192) ? 2 : (col >= 96 ? 1 : 0);
                int rem = col - sec * 96;
                int h   = (rem * 171) >> 11;
                int d   = rem - h * 12;
                float vs = (sec == 0) ? SCALE : 1.f;     // fold softmax scale into Q
                int base = h * 384 + sec * 128 + gi * 8 + (((d >> 1)) ^ xgi);
                #pragma unroll
                for (int wd = 0; wd < 2; wd++) {
                    int wb = (wp * 2 + wd) * 3072;
                    QF[wb + base]      = p16(c[wd][0] * vs, c[wd][1] * vs);
                    QF[wb + base + 64] = p16(c[wd][2] * vs, c[wd][3] * vs);  // row gi+8
                }
            }
        }
        __syncthreads();

        // ===== Attention: warp = (window aw, head quad hg), ldmatrix + mma =====
        {
            const int wb = aw * 3072;
            u32 hbase = sb + (u32)(wb + hg * 384) * 4;   // byte base of first head
            const float* mrow = mask + (size_t)((g * 4 + aw) % L_DIM) * 256;
            float2 mk00 = *(const float2*)(mrow + gi * 16 + 2 * tg);
            float2 mk01 = *(const float2*)(mrow + gi * 16 + 8 + 2 * tg);
            float2 mk10 = *(const float2*)(mrow + (gi + 8) * 16 + 2 * tg);
            float2 mk11 = *(const float2*)(mrow + (gi + 8) * 16 + 8 + 2 * tg);
            const __half2* RB2 = (const __half2*)RBH;

            #pragma unroll 2
            for (int hh = 0; hh < 4; hh++) {
                const int h = hg + hh;
                u32 qa0, qa1, qa2, qa3, k0, k1, k2, k3, v0, v1, v2, v3;
                ldsm4 (qa0, qa1, qa2, qa3, hbase + offQ);
                ldsm4 (k0, k1, k2, k3, hbase + offK);
                ldsm4t(v0, v1, v2, v3, hbase + offV);

                float2 b00 = __half22float2(__ldg(RB2 + h * 128 + gi * 8 + tg));
                float2 b01 = __half22float2(__ldg(RB2 + h * 128 + gi * 8 + tg + 4));
                float2 b10 = __half22float2(__ldg(RB2 + h * 128 + (gi + 8) * 8 + tg));
                float2 b11 = __half22float2(__ldg(RB2 + h * 128 + (gi + 8) * 8 + tg + 4));

                float c00 = mk00.x + b00.x, c01 = mk00.y + b00.y;
                float c02 = mk10.x + b10.x, c03 = mk10.y + b10.y;
                float c10 = mk01.x + b01.x, c11 = mk01.y + b01.y;
                float c12 = mk11.x + b11.x, c13 = mk11.y + b11.y;
                mma16(c00, c01, c02, c03, qa0, qa1, qa2, qa3, k0, k1);
                mma16(c10, c11, c12, c13, qa0, qa1, qa2, qa3, k2, k3);

                // no max-subtraction: |scores| <= ~6 (mask-dominated), exp is safe
                float e00 = __expf(c00), e01 = __expf(c01);
                float e02 = __expf(c02), e03 = __expf(c03);
                float e10 = __expf(c10), e11 = __expf(c11);
                float e12 = __expf(c12), e13 = __expf(c13);

                u32 pa0 = p16(e00, e01), pa1 = p16(e02, e03);
                u32 pa2 = p16(e10, e11), pa3 = p16(e12, e13);

                float o00 = 0, o01 = 0, o02 = 0, o03 = 0;
                float o10 = 0, o11 = 0, o12 = 0, o13 = 0;
                mma16(o00, o01, o02, o03, pa0, pa1, pa2, pa3, v0, v1);
                mma16(o10, o11, o12, o13, pa0, pa1, pa2, pa3, v2, v3);

                // row sums arrive at col 12 (ones column)
                float slo = __shfl_sync(0xffffffffu, o10, srcln);
                float shi = __shfl_sync(0xffffffffu, o12, srcln);
                float invlo = __fdividef(1.f, slo);
                float invhi = __fdividef(1.f, shi);

                // store attn-out into this quad's own AF half (race-free)
                int col0 = h * 12 + 2 * tg;
                int ks0  = col0 >> 4;
                int p0   = (col0 >> 3) & 1;
                int lt0  = gi * 4 + ((col0 & 7) >> 1);
                uint2 sv0;
                sv0.x = p16(o00 * invlo, o01 * invlo);
                sv0.y = p16(o02 * invhi, o03 * invhi);
                *(uint2*)&QF[wb + afoff(ks0) + p0 * 64 + lt0 * 2] = sv0;
                if (tg < 2) {
                    int col1 = col0 + 8;
                    int ks1  = col1 >> 4;
                    int p1   = (col1 >> 3) & 1;
                    int lt1  = gi * 4 + ((col1 & 7) >> 1);
                    uint2 sv1;
                    sv1.x = p16(o10 * invlo, o11 * invlo);
                    sv1.y = p16(o12 * invhi, o13 * invhi);
                    *(uint2*)&QF[wb + afoff(ks1) + p1 * 64 + lt1 * 2] = sv1;
                }
                hbase += 1536;
            }
        }
        __syncthreads();

        // ================= Proj GEMM (A frags as LDS.64 pairs from AF) ==========
        {
            u32 pf[2][6][4];
            #pragma unroll
            for (int wd = 0; wd < 2; wd++) {
                const int wb = (wp * 2 + wd) * 3072;
                #pragma unroll
                for (int ks = 0; ks < 6; ks++) {
                    uint2 L0 = *(const uint2*)&QF[wb + afoff(ks) + ln * 2];
                    uint2 L1 = *(const uint2*)&QF[wb + afoff(ks) + 64 + ln * 2];
                    pf[wd][ks][0] = L0.x; pf[wd][ks][1] = L0.y;
                    pf[wd][ks][2] = L1.x; pf[wd][ks][3] = L1.y;
                }
            }
            #pragma unroll
            for (int j = 0; j < 3; j++) {
                const int cq = cs * 3 + j;
                float2 bb = *(const float2*)&BPs[cq * 8 + 2 * tg];
                float c[2][4];
                c[0][0] = bb.x; c[0][1] = bb.y; c[0][2] = bb.x; c[0][3] = bb.y;
                c[1][0] = bb.x; c[1][1] = bb.y; c[1][2] = bb.x; c[1][3] = bb.y;
                const u32* bp = PRJG + (size_t)cq * 384 + ln * 4;
                #pragma unroll
                for (int ks2 = 0; ks2 < 3; ks2++) {
                    uint4 bv = __ldg((const uint4*)(bp + ks2 * 128));
                    mma16(c[0][0], c[0][1], c[0][2], c[0][3],
                          pf[0][2*ks2][0], pf[0][2*ks2][1], pf[0][2*ks2][2], pf[0][2*ks2][3],
                          bv.x, bv.y);
                    mma16(c[1][0], c[1][1], c[1][2], c[1][3],
                          pf[1][2*ks2][0], pf[1][2*ks2][1], pf[1][2*ks2][2], pf[1][2*ks2][3],
                          bv.x, bv.y);
                    mma16(c[0][0], c[0][1], c[0][2], c[0][3],
                          pf[0][2*ks2+1][0], pf[0][2*ks2+1][1], pf[0][2*ks2+1][2], pf[0][2*ks2+1][3],
                          bv.z, bv.w);
                    mma16(c[1][0], c[1][1], c[1][2], c[1][3],
                          pf[1][2*ks2+1][0], pf[1][2*ks2+1][1], pf[1][2*ks2+1][2], pf[1][2*ks2+1][3],
                          bv.z, bv.w);
                }
                #pragma unroll
                for (int wd = 0; wd < 2; wd++) {
                    float* og = out + ((size_t)g * 64 + (wp * 2 + wd) * 16 + gi) * 96
                                    + cq * 8 + 2 * tg;
                    *(float2*)og            = make_float2(c[wd][0], c[wd][1]);
                    *(float2*)(og + 8 * 96) = make_float2(c[wd][2], c[wd][3]);
                }
            }
        }
        __syncthreads();   // QF reuse by next tile
    }
}

extern "C" void kernel_launch(void* const* d_in, const int* in_sizes, int n_in,
                              void* d_out, int out_size)
{
    const float* x          = (const float*)d_in[0];
    const float* mask       = (const float*)d_in[1];
    const float* qkv_w      = (const float*)d_in[2];
    const float* qkv_b      = (const float*)d_in[3];
    const float* proj_w     = (const float*)d_in[4];
    const float* proj_b     = (const float*)d_in[5];
    const float* bias_table = (const float*)d_in[6];
    float* out = (float*)d_out;

    int sms = 148;
    cudaDeviceGetAttribute(&sms, cudaDevAttrMultiProcessorCount, 0);
    cudaFuncSetAttribute(win_attn_kernel,
                         cudaFuncAttributeMaxDynamicSharedMemorySize, SMEM_BYTES);

    win_attn_kernel<<<2 * sms, 256, SMEM_BYTES>>>(x, mask, qkv_w, qkv_b,
                                                  proj_w, proj_b, bias_table, out);
}

// round 16
// speedup vs baseline: 1.1965x; 1.1965x over previous
#include <cuda_runtime.h>
#include <cuda_fp16.h>

// WindowAttention: fully tensor-core (fp16 m16n8k16), ldmatrix-native SMEM.
// 50176 windows of [16 tok, 96 ch], H=8, D=12. 4 warps/CTA, 4 CTAs/SM, tile=4 windows.
// B-packs in GLOBAL (L2-resident; SMEM variant measured slower). rel-bias in SMEM.
// Softmax in log2 domain: log2e folded into Q scale, rb pack, and mask FMA; exp = ex2.
// QF per window: 8 heads x 384 u32 { Q[16 rows] | K | V }.
//   XOR swizzle: row r, slot s -> u32 offset 8r + (s ^ (r & 4)).
//   pad slots 6,7 zero, except V slot6 = (1.0h,0) -> ones col d=12
//   (PV mma emits the softmax row-sum at col 12).
// AF (attn-out, proj-A frags) aliases first 768 u32 of each window block.

#define NWIN   50176
#define NTILES (NWIN / 4)      // 12544
#define L_DIM  3136
#define SCALE  0.28867513459481287f
#define L2E    1.4426950408889634f
#define QSL2E  (0.28867513459481287f * 1.4426950408889634f)

#define QF_U32   12288                 // 4 windows * 3072
#define OFF_RB   (QF_U32 * 4)          // 49152: rel-bias half2, 1024 u32 = 4096 B
#define OFF_BQ   (OFF_RB + 4096)       // 53248: qkv_bias 288 f32
#define OFF_BP   (OFF_BQ + 1152)       // proj_bias 96 f32
#define SMEM_BYTES (OFF_BP + 384)      // 54784

typedef unsigned int u32;

__device__ u32 PQG[36 * 6 * 64];       // QKV B-pack: [cq][ks2][ln][4]
__device__ u32 PRJG[12 * 6 * 64];      // proj B-pack, same scheme

__device__ __forceinline__ u32 p16(float a, float b) {
    __half2 h = __floats2half2_rn(a, b);
    return *(u32*)&h;
}
__device__ __forceinline__ float ex2(float x) {
    float y; asm("ex2.approx.ftz.f32 %0, %1;" : "=f"(y) : "f"(x)); return y;
}
__device__ __forceinline__ u32 smem_u32(const void* p) {
    u32 a;
    asm("{ .reg .u64 t; cvta.to.shared.u64 t, %1; cvt.u32.u64 %0, t; }" : "=r"(a) : "l"(p));
    return a;
}
__device__ __forceinline__ void mma16(float& c0, float& c1, float& c2, float& c3,
                                      u32 a0, u32 a1, u32 a2, u32 a3,
                                      u32 b0, u32 b1) {
    asm volatile(
        "mma.sync.aligned.m16n8k16.row.col.f32.f16.f16.f32 "
        "{%0,%1,%2,%3}, {%4,%5,%6,%7}, {%8,%9}, {%0,%1,%2,%3};"
        : "+f"(c0), "+f"(c1), "+f"(c2), "+f"(c3)
        : "r"(a0), "r"(a1), "r"(a2), "r"(a3), "r"(b0), "r"(b1));
}
__device__ __forceinline__ void ldsm4(u32& r0, u32& r1, u32& r2, u32& r3, u32 a) {
    asm volatile("ldmatrix.sync.aligned.m8n8.x4.shared.b16 {%0,%1,%2,%3}, [%4];"
        : "=r"(r0), "=r"(r1), "=r"(r2), "=r"(r3) : "r"(a));
}
__device__ __forceinline__ void ldsm4t(u32& r0, u32& r1, u32& r2, u32& r3, u32 a) {
    asm volatile("ldmatrix.sync.aligned.m8n8.x4.trans.shared.b16 {%0,%1,%2,%3}, [%4];"
        : "=r"(r0), "=r"(r1), "=r"(r2), "=r"(r3) : "r"(a));
}

__global__ __launch_bounds__(128, 4)
void win_attn_kernel(const float* __restrict__ x,
                     const float* __restrict__ mask,
                     const float* __restrict__ qkv_w,
                     const float* __restrict__ qkv_b,
                     const float* __restrict__ proj_w,
                     const float* __restrict__ proj_b,
                     const float* __restrict__ bias_table,
                     float* __restrict__ out)
{
    extern __shared__ char smb[];
    u32*     QF   = (u32*)smb;
    __half2* RBL2 = (__half2*)(smb + OFF_RB);
    float*   BQs  = (float*)(smb + OFF_BQ);
    float*   BPs  = (float*)(smb + OFF_BP);
    const u32 sb = smem_u32(smb);

    const int t = threadIdx.x;

    // ---- One-time staging ----
    for (int i = t; i < QF_U32; i += 128) QF[i] = 0;
    __syncthreads();
    for (int i = t; i < 512; i += 128) {            // V ones col (d=12, slot 6)
        int win = i >> 7, h = (i >> 4) & 7, row = i & 15;
        QF[win * 3072 + h * 384 + 256 + row * 8 + (6 ^ (row & 4))] = 0x00003C00u;
    }
    for (int i = t; i < 36 * 6 * 32; i += 128) {
        int cq = i / 192, r = i % 192, ks = r / 32, lnn = r % 32;
        int gg = lnn >> 2, tt = lnn & 3;
        int k0 = ks * 16 + 2 * tt, n = cq * 8 + gg;
        int dst = cq * 384 + (ks >> 1) * 128 + lnn * 4 + (ks & 1) * 2;
        PQG[dst + 0] = p16(qkv_w[k0 * 288 + n],       qkv_w[(k0 + 1) * 288 + n]);
        PQG[dst + 1] = p16(qkv_w[(k0 + 8) * 288 + n], qkv_w[(k0 + 9) * 288 + n]);
    }
    for (int i = t; i < 12 * 6 * 32; i += 128) {
        int cq = i / 192, r = i % 192, ks = r / 32, lnn = r % 32;
        int gg = lnn >> 2, tt = lnn & 3;
        int k0 = ks * 16 + 2 * tt, n = cq * 8 + gg;
        int dst = cq * 384 + (ks >> 1) * 128 + lnn * 4 + (ks & 1) * 2;
        PRJG[dst + 0] = p16(proj_w[k0 * 96 + n],       proj_w[(k0 + 1) * 96 + n]);
        PRJG[dst + 1] = p16(proj_w[(k0 + 8) * 96 + n], proj_w[(k0 + 9) * 96 + n]);
    }
    // rel-bias (x log2e) -> SMEM half2, XOR-4 bank swizzle on j2
    for (int i = t; i < 1024; i += 128) {
        int h = i >> 7, ii = (i >> 3) & 15, j2 = i & 7;
        int j0 = 2 * j2, j1 = 2 * j2 + 1;
        int d00 = (ii & 3) - (j0 & 3) + 3, d10 = (ii >> 2) - (j0 >> 2) + 3;
        int d01 = (ii & 3) - (j1 & 3) + 3, d11 = (ii >> 2) - (j1 >> 2) + 3;
        int dst = h * 128 + ii * 8 + (j2 ^ (((ii >> 2) & 1) * 4));
        RBL2[dst] = __floats2half2_rn(bias_table[(d00 * 7 + d10) * 8 + h] * L2E,
                                      bias_table[(d01 * 7 + d11) * 8 + h] * L2E);
    }
    for (int i = t; i < 288; i += 128) BQs[i] = qkv_b[i];
    if (t < 96) BPs[t] = proj_b[t];
    __syncthreads();

    const int wid = t >> 5;
    const int ln  = t & 31;
    const int gi  = ln >> 2;
    const int tg  = ln & 3;
    const int wp  = wid >> 1;       // window pair for GEMM phases
    const int cs  = wid & 1;        // chunk half
    const int xgi = gi & 4;         // epilogue slot-XOR bit

    // ldmatrix lane byte-offsets (within a head block), XOR-swizzled halves
    const int rQ = ln & 15;
    const u32 offQ = (u32)(rQ * 32 + ((((ln >> 4) & 1) << 4) ^ ((rQ & 4) << 2)));
    const int rK = (ln & 7) | (((ln >> 4) & 1) << 3);
    const u32 offK = (u32)(rK * 32 + ((((ln >> 3) & 1) << 4) ^ ((rK & 4) << 2)) + 512);
    const u32 offV = offQ + 1024;
    const int srcln = (ln & ~3) | 2;      // shuffle source: lane holding col 12

    // swizzled rb lane offsets
    const int x4 = ((gi >> 2) & 1) * 4;
    const int rb_lo0 = gi * 8 + (tg ^ x4);
    const int rb_lo1 = gi * 8 + ((tg + 4) ^ x4);
    const int rb_hi0 = (gi + 8) * 8 + (tg ^ x4);
    const int rb_hi1 = (gi + 8) * 8 + ((tg + 4) ^ x4);

    for (int g = blockIdx.x; g < NTILES; g += gridDim.x) {
        // ================= QKV GEMM -> swizzled row-major head blocks ==========
        {
            u32 af[2][6][4];
            #pragma unroll
            for (int wd = 0; wd < 2; wd++) {
                const float* xr = x + ((size_t)g * 64 + (wp * 2 + wd) * 16 + gi) * 96;
                #pragma unroll
                for (int ks = 0; ks < 6; ks++) {
                    float2 v0 = *(const float2*)(xr + ks * 16 + 2 * tg);
                    float2 v1 = *(const float2*)(xr + 768 + ks * 16 + 2 * tg);
                    float2 v2 = *(const float2*)(xr + ks * 16 + 2 * tg + 8);
                    float2 v3 = *(const float2*)(xr + 768 + ks * 16 + 2 * tg + 8);
                    af[wd][ks][0] = p16(v0.x, v0.y);
                    af[wd][ks][1] = p16(v1.x, v1.y);
                    af[wd][ks][2] = p16(v2.x, v2.y);
                    af[wd][ks][3] = p16(v3.x, v3.y);
                }
            }
            // refresh pad slots of heads 0,1 (trampled by last tile's AF)
            for (int i = t; i < 768; i += 128) {
                int win = i / 192, r = i % 192;
                int h = r / 96, r2 = r % 96, sec = r2 >> 5, r3 = r2 & 31;
                int row = r3 >> 1, slot = 6 + (r3 & 1);
                QF[win * 3072 + h * 384 + sec * 128 + row * 8 + (slot ^ (row & 4))] =
                    (sec == 2 && slot == 6) ? 0x00003C00u : 0u;
            }
            #pragma unroll
            for (int j = 0; j < 18; j++) {
                const int cq = cs * 18 + j;
                float2 bb = *(const float2*)&BQs[cq * 8 + 2 * tg];
                float c[2][4];
                c[0][0] = bb.x; c[0][1] = bb.y; c[0][2] = bb.x; c[0][3] = bb.y;
                c[1][0] = bb.x; c[1][1] = bb.y; c[1][2] = bb.x; c[1][3] = bb.y;
                const u32* bp = PQG + (size_t)cq * 384 + ln * 4;
                #pragma unroll
                for (int ks2 = 0; ks2 < 3; ks2++) {
                    uint4 bv = __ldg((const uint4*)(bp + ks2 * 128));
                    mma16(c[0][0], c[0][1], c[0][2], c[0][3],
                          af[0][2*ks2][0], af[0][2*ks2][1], af[0][2*ks2][2], af[0][2*ks2][3],
                          bv.x, bv.y);
                    mma16(c[1][0], c[1][1], c[1][2], c[1][3],
                          af[1][2*ks2][0], af[1][2*ks2][1], af[1][2*ks2][2], af[1][2*ks2][3],
                          bv.x, bv.y);
                    mma16(c[0][0], c[0][1], c[0][2], c[0][3],
                          af[0][2*ks2+1][0], af[0][2*ks2+1][1], af[0][2*ks2+1][2], af[0][2*ks2+1][3],
                          bv.z, bv.w);
                    mma16(c[1][0], c[1][1], c[1][2], c[1][3],
                          af[1][2*ks2+1][0], af[1][2*ks2+1][1], af[1][2*ks2+1][2], af[1][2*ks2+1][3],
                          bv.z, bv.w);
                }
                int col = cq * 8 + 2 * tg;
                int sec = (col >= 192) ? 2 : (col >= 96 ? 1 : 0);
                int rem = col - sec * 96;
                int h   = (rem * 171) >> 11;
                int d   = rem - h * 12;
                // fold softmax scale AND log2e into Q
                float vs = (sec == 0) ? QSL2E : 1.f;
                int base = h * 384 + sec * 128 + gi * 8 + (((d >> 1)) ^ xgi);
                #pragma unroll
                for (int wd = 0; wd < 2; wd++) {
                    int wb = (wp * 2 + wd) * 3072;
                    QF[wb + base]      = p16(c[wd][0] * vs, c[wd][1] * vs);
                    QF[wb + base + 64] = p16(c[wd][2] * vs, c[wd][3] * vs);  // row gi+8
                }
            }
        }
        __syncthreads();

        // ======= Attention: ldmatrix + mma, log2-domain softmax, ones-col sum ==
        {
            const int aw = wid;                    // warp = window
            const int wb = aw * 3072;
            const u32 hb0 = sb + (u32)wb * 4;      // byte base of head 0 block
            const float* mrow = mask + (size_t)((g * 4 + aw) % L_DIM) * 256;
            float2 mk00 = *(const float2*)(mrow + gi * 16 + 2 * tg);
            float2 mk01 = *(const float2*)(mrow + gi * 16 + 8 + 2 * tg);
            float2 mk10 = *(const float2*)(mrow + (gi + 8) * 16 + 2 * tg);
            float2 mk11 = *(const float2*)(mrow + (gi + 8) * 16 + 8 + 2 * tg);

            #pragma unroll
            for (int h = 0; h < 8; h++) {
                const u32 hbase = hb0 + (u32)h * 1536;
                u32 qa0, qa1, qa2, qa3, k0, k1, k2, k3, v0, v1, v2, v3;
                ldsm4 (qa0, qa1, qa2, qa3, hbase + offQ);
                ldsm4 (k0, k1, k2, k3, hbase + offK);
                ldsm4t(v0, v1, v2, v3, hbase + offV);

                float2 b00 = __half22float2(RBL2[h * 128 + rb_lo0]);
                float2 b01 = __half22float2(RBL2[h * 128 + rb_lo1]);
                float2 b10 = __half22float2(RBL2[h * 128 + rb_hi0]);
                float2 b11 = __half22float2(RBL2[h * 128 + rb_hi1]);

                float c00 = fmaf(mk00.x, L2E, b00.x), c01 = fmaf(mk00.y, L2E, b00.y);
                float c02 = fmaf(mk10.x, L2E, b10.x), c03 = fmaf(mk10.y, L2E, b10.y);
                float c10 = fmaf(mk01.x, L2E, b01.x), c11 = fmaf(mk01.y, L2E, b01.y);
                float c12 = fmaf(mk11.x, L2E, b11.x), c13 = fmaf(mk11.y, L2E, b11.y);
                mma16(c00, c01, c02, c03, qa0, qa1, qa2, qa3, k0, k1);
                mma16(c10, c11, c12, c13, qa0, qa1, qa2, qa3, k2, k3);

                // no max-subtraction: |scores(log2)| <= ~9, ex2 is safe in fp32
                float e00 = ex2(c00), e01 = ex2(c01);
                float e02 = ex2(c02), e03 = ex2(c03);
                float e10 = ex2(c10), e11 = ex2(c11);
                float e12 = ex2(c12), e13 = ex2(c13);

                u32 pa0 = p16(e00, e01), pa1 = p16(e02, e03);
                u32 pa2 = p16(e10, e11), pa3 = p16(e12, e13);

                float o00 = 0, o01 = 0, o02 = 0, o03 = 0;
                float o10 = 0, o11 = 0, o12 = 0, o13 = 0;
                mma16(o00, o01, o02, o03, pa0, pa1, pa2, pa3, v0, v1);
                mma16(o10, o11, o12, o13, pa0, pa1, pa2, pa3, v2, v3);

                // row sums arrive at col 12 (ones column) -> lane tg=2 regs o10/o12
                float slo = __shfl_sync(0xffffffffu, o10, srcln);
                float shi = __shfl_sync(0xffffffffu, o12, srcln);
                float invlo = __fdividef(1.f, slo);
                float invhi = __fdividef(1.f, shi);

                // store attn-out in paired proj-A-frag order (AF aliases QF prefix)
                int col0 = h * 12 + 2 * tg;
                int ks0  = col0 >> 4;
                int p0   = (col0 >> 3) & 1;
                int lt0  = gi * 4 + ((col0 & 7) >> 1);
                uint2 sv0;
                sv0.x = p16(o00 * invlo, o01 * invlo);
                sv0.y = p16(o02 * invhi, o03 * invhi);
                *(uint2*)&QF[wb + ks0 * 128 + p0 * 64 + lt0 * 2] = sv0;
                if (tg < 2) {
                    int col1 = col0 + 8;
                    int ks1  = col1 >> 4;
                    int p1   = (col1 >> 3) & 1;
                    int lt1  = gi * 4 + ((col1 & 7) >> 1);
                    uint2 sv1;
                    sv1.x = p16(o10 * invlo, o11 * invlo);
                    sv1.y = p16(o12 * invhi, o13 * invhi);
                    *(uint2*)&QF[wb + ks1 * 128 + p1 * 64 + lt1 * 2] = sv1;
                }
            }
        }
        __syncthreads();

        // ================= Proj GEMM (A frags as LDS.64 pairs from AF) ==========
        {
            u32 pf[2][6][4];
            #pragma unroll
            for (int wd = 0; wd < 2; wd++) {
                const int wb = (wp * 2 + wd) * 3072;
                #pragma unroll
                for (int ks = 0; ks < 6; ks++) {
                    uint2 L0 = *(const uint2*)&QF[wb + ks * 128 + ln * 2];
                    uint2 L1 = *(const uint2*)&QF[wb + ks * 128 + 64 + ln * 2];
                    pf[wd][ks][0] = L0.x; pf[wd][ks][1] = L0.y;
                    pf[wd][ks][2] = L1.x; pf[wd][ks][3] = L1.y;
                }
            }
            #pragma unroll
            for (int j = 0; j < 6; j++) {
                const int cq = cs * 6 + j;
                float2 bb = *(const float2*)&BPs[cq * 8 + 2 * tg];
                float c[2][4];
                c[0][0] = bb.x; c[0][1] = bb.y; c[0][2] = bb.x; c[0][3] = bb.y;
                c[1][0] = bb.x; c[1][1] = bb.y; c[1][2] = bb.x; c[1][3] = bb.y;
                const u32* bp = PRJG + (size_t)cq * 384 + ln * 4;
                #pragma unroll
                for (int ks2 = 0; ks2 < 3; ks2++) {
                    uint4 bv = __ldg((const uint4*)(bp + ks2 * 128));
                    mma16(c[0][0], c[0][1], c[0][2], c[0][3],
                          pf[0][2*ks2][0], pf[0][2*ks2][1], pf[0][2*ks2][2], pf[0][2*ks2][3],
                          bv.x, bv.y);
                    mma16(c[1][0], c[1][1], c[1][2], c[1][3],
                          pf[1][2*ks2][0], pf[1][2*ks2][1], pf[1][2*ks2][2], pf[1][2*ks2][3],
                          bv.x, bv.y);
                    mma16(c[0][0], c[0][1], c[0][2], c[0][3],
                          pf[0][2*ks2+1][0], pf[0][2*ks2+1][1], pf[0][2*ks2+1][2], pf[0][2*ks2+1][3],
                          bv.z, bv.w);
                    mma16(c[1][0], c[1][1], c[1][2], c[1][3],
                          pf[1][2*ks2+1][0], pf[1][2*ks2+1][1], pf[1][2*ks2+1][2], pf[1][2*ks2+1][3],
                          bv.z, bv.w);
                }
                #pragma unroll
                for (int wd = 0; wd < 2; wd++) {
                    float* og = out + ((size_t)g * 64 + (wp * 2 + wd) * 16 + gi) * 96
                                    + cq * 8 + 2 * tg;
                    *(float2*)og            = make_float2(c[wd][0], c[wd][1]);
                    *(float2*)(og + 8 * 96) = make_float2(c[wd][2], c[wd][3]);
                }
            }
        }
        __syncthreads();   // QF reuse by next tile
    }
}

extern "C" void kernel_launch(void* const* d_in, const int* in_sizes, int n_in,
                              void* d_out, int out_size)
{
    const float* x          = (const float*)d_in[0];
    const float* mask       = (const float*)d_in[1];
    const float* qkv_w      = (const float*)d_in[2];
    const float* qkv_b      = (const float*)d_in[3];
    const float* proj_w     = (const float*)d_in[4];
    const float* proj_b     = (const float*)d_in[5];
    const float* bias_table = (const float*)d_in[6];
    float* out = (float*)d_out;

    int sms = 148;
    cudaDeviceGetAttribute(&sms, cudaDevAttrMultiProcessorCount, 0);
    cudaFuncSetAttribute(win_attn_kernel,
                         cudaFuncAttributeMaxDynamicSharedMemorySize, SMEM_BYTES);

    win_attn_kernel<<<4 * sms, 128, SMEM_BYTES>>>(x, mask, qkv_w, qkv_b,
                                                  proj_w, proj_b, bias_table, out);
}

// round 17
// speedup vs baseline: 1.2284x; 1.0266x over previous
#include <cuda_runtime.h>
#include <cuda_fp16.h>

// WindowAttention: fully tensor-core (fp16 m16n8k16), ldmatrix-native SMEM.
// 50176 windows of [16 tok, 96 ch], H=8, D=12. 4 warps/CTA, 4 CTAs/SM, tile=4 windows.
// PIPELINE IS WARP-PAIR-LOCAL: warps {0,1} own windows 0,1; warps {2,3} own 2,3.
// All per-tile syncs are pair-scoped named barriers (bar.sync id,64) -> 8
// independently-phased 2-window pipelines per SM.
// B-packs in GLOBAL (L2-resident). rel-bias in SMEM. log2-domain softmax.
// QF per window: 8 heads x 384 u32 { Q[16 rows] | K | V }.
//   XOR swizzle: row r, slot s -> u32 offset 8r + (s ^ (r & 4)).
//   pad slots 6,7 zero, except V slot6 = (1.0h,0) -> ones col d=12
//   (PV mma emits the softmax row-sum at col 12).
// AF (attn-out, proj-A frags) aliases first 768 u32 of each window block.

#define NWIN   50176
#define NTILES (NWIN / 4)      // 12544
#define L_DIM  3136
#define L2E    1.4426950408889634f
#define QSL2E  (0.28867513459481287f * 1.4426950408889634f)

#define QF_U32   12288                 // 4 windows * 3072
#define OFF_RB   (QF_U32 * 4)          // 49152: rel-bias half2, 1024 u32 = 4096 B
#define OFF_BQ   (OFF_RB + 4096)       // 53248: qkv_bias 288 f32
#define OFF_BP   (OFF_BQ + 1152)       // proj_bias 96 f32
#define SMEM_BYTES (OFF_BP + 384)      // 54784

typedef unsigned int u32;

__device__ u32 PQG[36 * 6 * 64];       // QKV B-pack: [cq][ks2][ln][4]
__device__ u32 PRJG[12 * 6 * 64];      // proj B-pack, same scheme

__device__ __forceinline__ u32 p16(float a, float b) {
    __half2 h = __floats2half2_rn(a, b);
    return *(u32*)&h;
}
__device__ __forceinline__ float ex2(float x) {
    float y; asm("ex2.approx.ftz.f32 %0, %1;" : "=f"(y) : "f"(x)); return y;
}
__device__ __forceinline__ u32 smem_u32(const void* p) {
    u32 a;
    asm("{ .reg .u64 t; cvta.to.shared.u64 t, %1; cvt.u32.u64 %0, t; }" : "=r"(a) : "l"(p));
    return a;
}
__device__ __forceinline__ void mma16(float& c0, float& c1, float& c2, float& c3,
                                      u32 a0, u32 a1, u32 a2, u32 a3,
                                      u32 b0, u32 b1) {
    asm volatile(
        "mma.sync.aligned.m16n8k16.row.col.f32.f16.f16.f32 "
        "{%0,%1,%2,%3}, {%4,%5,%6,%7}, {%8,%9}, {%0,%1,%2,%3};"
        : "+f"(c0), "+f"(c1), "+f"(c2), "+f"(c3)
        : "r"(a0), "r"(a1), "r"(a2), "r"(a3), "r"(b0), "r"(b1));
}
__device__ __forceinline__ void ldsm4(u32& r0, u32& r1, u32& r2, u32& r3, u32 a) {
    asm volatile("ldmatrix.sync.aligned.m8n8.x4.shared.b16 {%0,%1,%2,%3}, [%4];"
        : "=r"(r0), "=r"(r1), "=r"(r2), "=r"(r3) : "r"(a));
}
__device__ __forceinline__ void ldsm4t(u32& r0, u32& r1, u32& r2, u32& r3, u32 a) {
    asm volatile("ldmatrix.sync.aligned.m8n8.x4.trans.shared.b16 {%0,%1,%2,%3}, [%4];"
        : "=r"(r0), "=r"(r1), "=r"(r2), "=r"(r3) : "r"(a));
}
__device__ __forceinline__ void pairbar(int id) {
    asm volatile("bar.sync %0, 64;" :: "r"(id) : "memory");
}

__global__ __launch_bounds__(128, 4)
void win_attn_kernel(const float* __restrict__ x,
                     const float* __restrict__ mask,
                     const float* __restrict__ qkv_w,
                     const float* __restrict__ qkv_b,
                     const float* __restrict__ proj_w,
                     const float* __restrict__ proj_b,
                     const float* __restrict__ bias_table,
                     float* __restrict__ out)
{
    extern __shared__ char smb[];
    u32*     QF   = (u32*)smb;
    __half2* RBL2 = (__half2*)(smb + OFF_RB);
    float*   BQs  = (float*)(smb + OFF_BQ);
    float*   BPs  = (float*)(smb + OFF_BP);
    const u32 sb = smem_u32(smb);

    const int t = threadIdx.x;

    // ---- One-time staging ----
    for (int i = t; i < QF_U32; i += 128) QF[i] = 0;
    __syncthreads();
    for (int i = t; i < 512; i += 128) {            // V ones col (d=12, slot 6)
        int win = i >> 7, h = (i >> 4) & 7, row = i & 15;
        QF[win * 3072 + h * 384 + 256 + row * 8 + (6 ^ (row & 4))] = 0x00003C00u;
    }
    for (int i = t; i < 36 * 6 * 32; i += 128) {
        int cq = i / 192, r = i % 192, ks = r / 32, lnn = r % 32;
        int gg = lnn >> 2, tt = lnn & 3;
        int k0 = ks * 16 + 2 * tt, n = cq * 8 + gg;
        int dst = cq * 384 + (ks >> 1) * 128 + lnn * 4 + (ks & 1) * 2;
        PQG[dst + 0] = p16(qkv_w[k0 * 288 + n],       qkv_w[(k0 + 1) * 288 + n]);
        PQG[dst + 1] = p16(qkv_w[(k0 + 8) * 288 + n], qkv_w[(k0 + 9) * 288 + n]);
    }
    for (int i = t; i < 12 * 6 * 32; i += 128) {
        int cq = i / 192, r = i % 192, ks = r / 32, lnn = r % 32;
        int gg = lnn >> 2, tt = lnn & 3;
        int k0 = ks * 16 + 2 * tt, n = cq * 8 + gg;
        int dst = cq * 384 + (ks >> 1) * 128 + lnn * 4 + (ks & 1) * 2;
        PRJG[dst + 0] = p16(proj_w[k0 * 96 + n],       proj_w[(k0 + 1) * 96 + n]);
        PRJG[dst + 1] = p16(proj_w[(k0 + 8) * 96 + n], proj_w[(k0 + 9) * 96 + n]);
    }
    // rel-bias (x log2e) -> SMEM half2, XOR-4 bank swizzle on j2
    for (int i = t; i < 1024; i += 128) {
        int h = i >> 7, ii = (i >> 3) & 15, j2 = i & 7;
        int j0 = 2 * j2, j1 = 2 * j2 + 1;
        int d00 = (ii & 3) - (j0 & 3) + 3, d10 = (ii >> 2) - (j0 >> 2) + 3;
        int d01 = (ii & 3) - (j1 & 3) + 3, d11 = (ii >> 2) - (j1 >> 2) + 3;
        int dst = h * 128 + ii * 8 + (j2 ^ (((ii >> 2) & 1) * 4));
        RBL2[dst] = __floats2half2_rn(bias_table[(d00 * 7 + d10) * 8 + h] * L2E,
                                      bias_table[(d01 * 7 + d11) * 8 + h] * L2E);
    }
    for (int i = t; i < 288; i += 128) BQs[i] = qkv_b[i];
    if (t < 96) BPs[t] = proj_b[t];
    __syncthreads();

    const int wid = t >> 5;
    const int ln  = t & 31;
    const int gi  = ln >> 2;
    const int tg  = ln & 3;
    const int wp  = wid >> 1;       // window pair (also pipeline id)
    const int cs  = wid & 1;        // chunk half
    const int xgi = gi & 4;         // epilogue slot-XOR bit
    const int bar = 1 + wp;         // pair-scoped named barrier id

    // ldmatrix lane byte-offsets (within a head block), XOR-swizzled halves
    const int rQ = ln & 15;
    const u32 offQ = (u32)(rQ * 32 + ((((ln >> 4) & 1) << 4) ^ ((rQ & 4) << 2)));
    const int rK = (ln & 7) | (((ln >> 4) & 1) << 3);
    const u32 offK = (u32)(rK * 32 + ((((ln >> 3) & 1) << 4) ^ ((rK & 4) << 2)) + 512);
    const u32 offV = offQ + 1024;
    const int srcln = (ln & ~3) | 2;      // shuffle source: lane holding col 12

    // swizzled rb lane offsets
    const int x4 = ((gi >> 2) & 1) * 4;
    const int rb_lo0 = gi * 8 + (tg ^ x4);
    const int rb_lo1 = gi * 8 + ((tg + 4) ^ x4);
    const int rb_hi0 = (gi + 8) * 8 + (tg ^ x4);
    const int rb_hi1 = (gi + 8) * 8 + ((tg + 4) ^ x4);

    // pad-refresh targets for this warp's own window (tile-invariant)
    const int padwin = (wp * 2 + cs) * 3072;

    for (int g = blockIdx.x; g < NTILES; g += gridDim.x) {
        // ================= QKV GEMM -> swizzled row-major head blocks ==========
        {
            u32 af[2][6][4];
            #pragma unroll
            for (int wd = 0; wd < 2; wd++) {
                const float* xr = x + ((size_t)g * 64 + (wp * 2 + wd) * 16 + gi) * 96;
                #pragma unroll
                for (int ks = 0; ks < 6; ks++) {
                    float2 v0 = *(const float2*)(xr + ks * 16 + 2 * tg);
                    float2 v1 = *(const float2*)(xr + 768 + ks * 16 + 2 * tg);
                    float2 v2 = *(const float2*)(xr + ks * 16 + 2 * tg + 8);
                    float2 v3 = *(const float2*)(xr + 768 + ks * 16 + 2 * tg + 8);
                    af[wd][ks][0] = p16(v0.x, v0.y);
                    af[wd][ks][1] = p16(v1.x, v1.y);
                    af[wd][ks][2] = p16(v2.x, v2.y);
                    af[wd][ks][3] = p16(v3.x, v3.y);
                }
            }
            // refresh pad slots of heads 0,1 of THIS warp's window (pair-local)
            #pragma unroll
            for (int s = 0; s < 6; s++) {
                int idx = ln + s * 32;               // 0..191
                int h   = (idx >= 96);
                int r2  = idx - h * 96;
                int sec = r2 >> 5, r3 = r2 & 31;
                int row = r3 >> 1, slot = 6 + (r3 & 1);
                QF[padwin + h * 384 + sec * 128 + row * 8 + (slot ^ (row & 4))] =
                    (sec == 2 && slot == 6) ? 0x00003C00u : 0u;
            }
            #pragma unroll
            for (int j = 0; j < 18; j++) {
                const int cq = cs * 18 + j;
                float2 bb = *(const float2*)&BQs[cq * 8 + 2 * tg];
                float c[2][4];
                c[0][0] = bb.x; c[0][1] = bb.y; c[0][2] = bb.x; c[0][3] = bb.y;
                c[1][0] = bb.x; c[1][1] = bb.y; c[1][2] = bb.x; c[1][3] = bb.y;
                const u32* bp = PQG + (size_t)cq * 384 + ln * 4;
                #pragma unroll
                for (int ks2 = 0; ks2 < 3; ks2++) {
                    uint4 bv = __ldg((const uint4*)(bp + ks2 * 128));
                    mma16(c[0][0], c[0][1], c[0][2], c[0][3],
                          af[0][2*ks2][0], af[0][2*ks2][1], af[0][2*ks2][2], af[0][2*ks2][3],
                          bv.x, bv.y);
                    mma16(c[1][0], c[1][1], c[1][2], c[1][3],
                          af[1][2*ks2][0], af[1][2*ks2][1], af[1][2*ks2][2], af[1][2*ks2][3],
                          bv.x, bv.y);
                    mma16(c[0][0], c[0][1], c[0][2], c[0][3],
                          af[0][2*ks2+1][0], af[0][2*ks2+1][1], af[0][2*ks2+1][2], af[0][2*ks2+1][3],
                          bv.z, bv.w);
                    mma16(c[1][0], c[1][1], c[1][2], c[1][3],
                          af[1][2*ks2+1][0], af[1][2*ks2+1][1], af[1][2*ks2+1][2], af[1][2*ks2+1][3],
                          bv.z, bv.w);
                }
                int col = cq * 8 + 2 * tg;
                int sec = (col >= 192) ? 2 : (col >= 96 ? 1 : 0);
                int rem = col - sec * 96;
                int h   = (rem * 171) >> 11;
                int d   = rem - h * 12;
                // fold softmax scale AND log2e into Q
                float vs = (sec == 0) ? QSL2E : 1.f;
                int base = h * 384 + sec * 128 + gi * 8 + (((d >> 1)) ^ xgi);
                #pragma unroll
                for (int wd = 0; wd < 2; wd++) {
                    int wb = (wp * 2 + wd) * 3072;
                    QF[wb + base]      = p16(c[wd][0] * vs, c[wd][1] * vs);
                    QF[wb + base + 64] = p16(c[wd][2] * vs, c[wd][3] * vs);  // row gi+8
                }
            }
        }
        pairbar(bar);

        // ======= Attention: ldmatrix + mma, log2-domain softmax, ones-col sum ==
        {
            const int aw = wid;                    // warp = window
            const int wb = aw * 3072;
            const u32 hb0 = sb + (u32)wb * 4;      // byte base of head 0 block
            const float* mrow = mask + (size_t)((g * 4 + aw) % L_DIM) * 256;
            float2 mk00 = *(const float2*)(mrow + gi * 16 + 2 * tg);
            float2 mk01 = *(const float2*)(mrow + gi * 16 + 8 + 2 * tg);
            float2 mk10 = *(const float2*)(mrow + (gi + 8) * 16 + 2 * tg);
            float2 mk11 = *(const float2*)(mrow + (gi + 8) * 16 + 8 + 2 * tg);

            #pragma unroll
            for (int h = 0; h < 8; h++) {
                const u32 hbase = hb0 + (u32)h * 1536;
                u32 qa0, qa1, qa2, qa3, k0, k1, k2, k3, v0, v1, v2, v3;
                ldsm4 (qa0, qa1, qa2, qa3, hbase + offQ);
                ldsm4 (k0, k1, k2, k3, hbase + offK);
                ldsm4t(v0, v1, v2, v3, hbase + offV);

                float2 b00 = __half22float2(RBL2[h * 128 + rb_lo0]);
                float2 b01 = __half22float2(RBL2[h * 128 + rb_lo1]);
                float2 b10 = __half22float2(RBL2[h * 128 + rb_hi0]);
                float2 b11 = __half22float2(RBL2[h * 128 + rb_hi1]);

                float c00 = fmaf(mk00.x, L2E, b00.x), c01 = fmaf(mk00.y, L2E, b00.y);
                float c02 = fmaf(mk10.x, L2E, b10.x), c03 = fmaf(mk10.y, L2E, b10.y);
                float c10 = fmaf(mk01.x, L2E, b01.x), c11 = fmaf(mk01.y, L2E, b01.y);
                float c12 = fmaf(mk11.x, L2E, b11.x), c13 = fmaf(mk11.y, L2E, b11.y);
                mma16(c00, c01, c02, c03, qa0, qa1, qa2, qa3, k0, k1);
                mma16(c10, c11, c12, c13, qa0, qa1, qa2, qa3, k2, k3);

                // no max-subtraction: |scores(log2)| <= ~9, ex2 is safe in fp32
                float e00 = ex2(c00), e01 = ex2(c01);
                float e02 = ex2(c02), e03 = ex2(c03);
                float e10 = ex2(c10), e11 = ex2(c11);
                float e12 = ex2(c12), e13 = ex2(c13);

                u32 pa0 = p16(e00, e01), pa1 = p16(e02, e03);
                u32 pa2 = p16(e10, e11), pa3 = p16(e12, e13);

                float o00 = 0, o01 = 0, o02 = 0, o03 = 0;
                float o10 = 0, o11 = 0, o12 = 0, o13 = 0;
                mma16(o00, o01, o02, o03, pa0, pa1, pa2, pa3, v0, v1);
                mma16(o10, o11, o12, o13, pa0, pa1, pa2, pa3, v2, v3);

                // row sums arrive at col 12 (ones column) -> lane tg=2 regs o10/o12
                float slo = __shfl_sync(0xffffffffu, o10, srcln);
                float shi = __shfl_sync(0xffffffffu, o12, srcln);
                float invlo = __fdividef(1.f, slo);
                float invhi = __fdividef(1.f, shi);

                // store attn-out in paired proj-A-frag order (AF aliases QF prefix)
                int col0 = h * 12 + 2 * tg;
                int ks0  = col0 >> 4;
                int p0   = (col0 >> 3) & 1;
                int lt0  = gi * 4 + ((col0 & 7) >> 1);
                uint2 sv0;
                sv0.x = p16(o00 * invlo, o01 * invlo);
                sv0.y = p16(o02 * invhi, o03 * invhi);
                *(uint2*)&QF[wb + ks0 * 128 + p0 * 64 + lt0 * 2] = sv0;
                if (tg < 2) {
                    int col1 = col0 + 8;
                    int ks1  = col1 >> 4;
                    int p1   = (col1 >> 3) & 1;
                    int lt1  = gi * 4 + ((col1 & 7) >> 1);
                    uint2 sv1;
                    sv1.x = p16(o10 * invlo, o11 * invlo);
                    sv1.y = p16(o12 * invhi, o13 * invhi);
                    *(uint2*)&QF[wb + ks1 * 128 + p1 * 64 + lt1 * 2] = sv1;
                }
            }
        }
        pairbar(bar);

        // ================= Proj GEMM (A frags as LDS.64 pairs from AF) ==========
        {
            u32 pf[2][6][4];
            #pragma unroll
            for (int wd = 0; wd < 2; wd++) {
                const int wb = (wp * 2 + wd) * 3072;
                #pragma unroll
                for (int ks = 0; ks < 6; ks++) {
                    uint2 L0 = *(const uint2*)&QF[wb + ks * 128 + ln * 2];
                    uint2 L1 = *(const uint2*)&QF[wb + ks * 128 + 64 + ln * 2];
                    pf[wd][ks][0] = L0.x; pf[wd][ks][1] = L0.y;
                    pf[wd][ks][2] = L1.x; pf[wd][ks][3] = L1.y;
                }
            }
            #pragma unroll
            for (int j = 0; j < 6; j++) {
                const int cq = cs * 6 + j;
                float2 bb = *(const float2*)&BPs[cq * 8 + 2 * tg];
                float c[2][4];
                c[0][0] = bb.x; c[0][1] = bb.y; c[0][2] = bb.x; c[0][3] = bb.y;
                c[1][0] = bb.x; c[1][1] = bb.y; c[1][2] = bb.x; c[1][3] = bb.y;
                const u32* bp = PRJG + (size_t)cq * 384 + ln * 4;
                #pragma unroll
                for (int ks2 = 0; ks2 < 3; ks2++) {
                    uint4 bv = __ldg((const uint4*)(bp + ks2 * 128));
                    mma16(c[0][0], c[0][1], c[0][2], c[0][3],
                          pf[0][2*ks2][0], pf[0][2*ks2][1], pf[0][2*ks2][2], pf[0][2*ks2][3],
                          bv.x, bv.y);
                    mma16(c[1][0], c[1][1], c[1][2], c[1][3],
                          pf[1][2*ks2][0], pf[1][2*ks2][1], pf[1][2*ks2][2], pf[1][2*ks2][3],
                          bv.x, bv.y);
                    mma16(c[0][0], c[0][1], c[0][2], c[0][3],
                          pf[0][2*ks2+1][0], pf[0][2*ks2+1][1], pf[0][2*ks2+1][2], pf[0][2*ks2+1][3],
                          bv.z, bv.w);
                    mma16(c[1][0], c[1][1], c[1][2], c[1][3],
                          pf[1][2*ks2+1][0], pf[1][2*ks2+1][1], pf[1][2*ks2+1][2], pf[1][2*ks2+1][3],
                          bv.z, bv.w);
                }
                #pragma unroll
                for (int wd = 0; wd < 2; wd++) {
                    float* og = out + ((size_t)g * 64 + (wp * 2 + wd) * 16 + gi) * 96
                                    + cq * 8 + 2 * tg;
                    *(float2*)og            = make_float2(c[wd][0], c[wd][1]);
                    *(float2*)(og + 8 * 96) = make_float2(c[wd][2], c[wd][3]);
                }
            }
        }
        pairbar(bar);   // QF reuse by next tile (pair-local)
    }
}

extern "C" void kernel_launch(void* const* d_in, const int* in_sizes, int n_in,
                              void* d_out, int out_size)
{
    const float* x          = (const float*)d_in[0];
    const float* mask       = (const float*)d_in[1];
    const float* qkv_w      = (const float*)d_in[2];
    const float* qkv_b      = (const float*)d_in[3];
    const float* proj_w     = (const float*)d_in[4];
    const float* proj_b     = (const float*)d_in[5];
    const float* bias_table = (const float*)d_in[6];
    float* out = (float*)d_out;

    int sms = 148;
    cudaDeviceGetAttribute(&sms, cudaDevAttrMultiProcessorCount, 0);
    cudaFuncSetAttribute(win_attn_kernel,
                         cudaFuncAttributeMaxDynamicSharedMemorySize, SMEM_BYTES);

    win_attn_kernel<<<4 * sms, 128, SMEM_BYTES>>>(x, mask, qkv_w, qkv_b,
                                                  proj_w, proj_b, bias_table, out);
}